// round 17
// baseline (speedup 1.0000x reference)
#include <cuda_runtime.h>
#include <cstdint>

// CoordsToNRF: out[b, p] = atoms_flat[p] * (AU2KCALMOLA / MAX_NRF) / ||c_i - c_j||^2
// p = i*(i-1)/2 + j over the strict lower triangle of 128 atoms. B=2048, NC2=8128.
//
// Round-17: R16 structure (flat chunks, consecutive-i dense stores, prescaled
// coords, partial/full loop split, 8 blocks/SM) with the inline-asm f32x2
// packed math replaced by plain scalar fp32. Hypothesis: the packed ops'
// even-register-pair operand constraint made ptxas emit ~20 MOVs/row; scalar
// FP is schedulable with zero shuffle at only 22%->~45% fma pipe cost.

#define N_ATOMS 128
#define NC2     8128
#define BLOCK_THREADS 256      // 8 warps, one batch PAIR per block

// sqrt(1 / (627.5095 * 0.529177 / 100.0)):
#define COORD_PRESCALE 0.5487683f

__global__ __launch_bounds__(BLOCK_THREADS, 8)
void coords_to_nrf_kernel(const float* __restrict__ coords,
                          const float* __restrict__ atoms_flat,
                          float* __restrict__ out) {
    // Packed pair coords (pre-scaled): atom a -> {x0,x1,y0,y1,z0,z1,pad,pad}.
    __shared__ __align__(16) float sc[N_ATOMS * 8];

    const int warp = threadIdx.x >> 5;    // 0..7 -> row chunk
    const int lane = threadIdx.x & 31;
    const int bg   = blockIdx.x;          // batch pair index

    // ---- Stage batch pair, pre-scaled by sqrt(1/scale) ----
    const float* cb = coords + (size_t)bg * 2 * (N_ATOMS * 3);
    #pragma unroll
    for (int idx = threadIdx.x; idx < 2 * N_ATOMS * 3; idx += BLOCK_THREADS) {
        const int q   = idx / (N_ATOMS * 3);       // batch in pair
        const int rem = idx - q * (N_ATOMS * 3);
        const int a   = rem / 3;
        const int d   = rem - a * 3;
        sc[a * 8 + d * 2 + q] = cb[idx] * COORD_PRESCALE;
    }
    __syncthreads();

    // Flat rows [0,316) split: 40,40,40,40,39,39,39,39.
    const int over = (warp > 4) ? (warp - 4) : 0;
    const int r0 = 40 * warp - over;
    const int r1 = r0 + ((warp < 4) ? 40 : 39);

    const int starts[5] = {0, 127, 222, 285, 316};

    float* ob = out + (size_t)bg * 2 * NC2;        // batch q=0 plane

    #pragma unroll
    for (int seg = 0; seg < 4; seg++) {
        const int a = (r0 > starts[seg])     ? r0 : starts[seg];
        const int b = (r1 < starts[seg + 1]) ? r1 : starts[seg + 1];
        if (a >= b) continue;

        const int j0 = seg * 32;
        const int j  = j0 + lane;

        // cj pair for both batches: 6 scalar registers.
        const float4 cjl = *reinterpret_cast<const float4*>(&sc[j * 8]);     // x0,x1,y0,y1
        const float2 cjh = *reinterpret_cast<const float2*>(&sc[j * 8 + 4]); // z0,z1
        const float cjx0 = cjl.x, cjx1 = cjl.y;
        const float cjy0 = cjl.z, cjy1 = cjl.w;
        const float cjz0 = cjh.x, cjz1 = cjh.y;

        const int i0   = j0 + 1 + (a - starts[seg]);
        const int iend = i0 + (b - a);
        // Rows with i < j0+32 are partial (per-lane mask); i >= j0+32 full.
        const int im_raw = j0 + 32;
        const int im = (iend < im_raw) ? iend : ((i0 > im_raw) ? i0 : im_raw);

        int pbase = (i0 * (i0 - 1)) >> 1;

        // ---- partial rows: clamp LDG, predicated stores ----
        #pragma unroll 4
        for (int i = i0; i < im; i++) {
            const float4 cil = *reinterpret_cast<const float4*>(&sc[i * 8]);
            const float2 cih = *reinterpret_cast<const float2*>(&sc[i * 8 + 4]);

            const float dx0 = cil.x - cjx0, dx1 = cil.y - cjx1;
            const float dy0 = cil.z - cjy0, dy1 = cil.w - cjy1;
            const float dz0 = cih.x - cjz0, dz1 = cih.y - cjz1;
            const float d20 = fmaf(dz0, dz0, fmaf(dy0, dy0, dx0 * dx0));
            const float d21 = fmaf(dz1, dz1, fmaf(dy1, dy1, dx1 * dx1));

            const int p  = pbase + j;
            const int pc = (p < NC2 - 1) ? p : (NC2 - 1);  // masked-lane safety
            const float aval = __ldg(&atoms_flat[pc]);     // scale folded in d2
            const float ra = __fdividef(aval, d20);         // batch 0
            const float rb = __fdividef(aval, d21);         // batch 1

            if (j < i) {               // bare predicated store pair -> @P STG
                ob[p]       = ra;
                ob[p + NC2] = rb;
            }
            pbase += i;
        }

        // ---- full rows: all 32 lanes valid, no clamp, no predicate ----
        #pragma unroll 8
        for (int i = im; i < iend; i++) {
            const float4 cil = *reinterpret_cast<const float4*>(&sc[i * 8]);
            const float2 cih = *reinterpret_cast<const float2*>(&sc[i * 8 + 4]);

            const float dx0 = cil.x - cjx0, dx1 = cil.y - cjx1;
            const float dy0 = cil.z - cjy0, dy1 = cil.w - cjy1;
            const float dz0 = cih.x - cjz0, dz1 = cih.y - cjz1;
            const float d20 = fmaf(dz0, dz0, fmaf(dy0, dy0, dx0 * dx0));
            const float d21 = fmaf(dz1, dz1, fmaf(dy1, dy1, dx1 * dx1));

            const int p = pbase + j;
            const float aval = __ldg(&atoms_flat[p]);

            ob[p]       = __fdividef(aval, d20);
            ob[p + NC2] = __fdividef(aval, d21);
            pbase += i;
        }
    }
}

extern "C" void kernel_launch(void* const* d_in, const int* in_sizes, int n_in,
                              void* d_out, int out_size) {
    const float* coords     = (const float*)d_in[0];  // [2048, 128, 3] f32
    const float* atoms_flat = (const float*)d_in[1];  // [8128] f32
    float* out = (float*)d_out;                       // [2048, 8128] f32

    const int batch = in_sizes[0] / (N_ATOMS * 3);    // 2048
    coords_to_nrf_kernel<<<batch / 2, BLOCK_THREADS>>>(coords, atoms_flat, out);
}